// round 6
// baseline (speedup 1.0000x reference)
#include <cuda_runtime.h>
#include <math.h>
#include <float.h>

#define N 4096
#define IN_F 256
#define H0 64
#define H1 64
#define H2 32
#define CAP 256
#define SLOPE 0.01f
#define WH_BLOCKS 192   // 64 row-tiles x 3 relations

// -------- scratch (device globals; no allocation) --------
__device__ int   g_nbr_idx[3 * N * CAP];
__device__ int   g_nbr_cnt[3 * N];
__device__ float g_Wh[3 * N * H0];
__device__ float g_ssrc[3 * N];
__device__ float g_sdst[3 * N];
__device__ float g_hr[3 * N * H0];
__device__ float g_support[N * H1];
__device__ float g_support2[N * H2];
__device__ float g_resid[N * H2];
__device__ float g_Wg1T[H2 * H1];   // Wg1 transposed to [j][k]

__device__ __forceinline__ float leaky(float v) { return v >= 0.f ? v : SLOPE * v; }

// ================= merged kernel 1: wh tiles + adj scan ===================
__device__ void wh_body(int b,
                        const float* __restrict__ x,
                        const float* __restrict__ W1, const float* __restrict__ a1,
                        const float* __restrict__ W2, const float* __restrict__ a2,
                        const float* __restrict__ W3, const float* __restrict__ a3) {
    int r = b >> 6;
    int row0 = (b & 63) * 64;
    const float* W = (r == 0) ? W1 : (r == 1) ? W2 : W3;
    const float* a = (r == 0) ? a1 : (r == 1) ? a2 : a3;
    int tid = threadIdx.x;
    int rg = tid >> 4;
    int cgp = tid & 15;

    __shared__ float sx[64][64];
    __shared__ float sW[64][64];

    float4 acc[4];
#pragma unroll
    for (int q = 0; q < 4; q++) acc[q] = make_float4(0.f, 0.f, 0.f, 0.f);

    for (int k0 = 0; k0 < IN_F; k0 += 64) {
        __syncthreads();
#pragma unroll
        for (int q = 0; q < 4; q++) {
            int lin = tid + q * 256;
            int rr = lin >> 4, c4 = (lin & 15) << 2;
            *(float4*)&sx[rr][c4] = *(const float4*)(x + (size_t)(row0 + rr) * IN_F + k0 + c4);
        }
#pragma unroll
        for (int q = 0; q < 4; q++) {
            int lin = tid + q * 256;
            int kr = lin >> 4, c4 = (lin & 15) << 2;
            *(float4*)&sW[kr][c4] = *(const float4*)(W + (size_t)(k0 + kr) * H0 + c4);
        }
        __syncthreads();
#pragma unroll 16
        for (int kk = 0; kk < 64; kk++) {
            float4 wv = *(float4*)&sW[kk][cgp * 4];
            float xv0 = sx[rg * 4 + 0][kk];
            float xv1 = sx[rg * 4 + 1][kk];
            float xv2 = sx[rg * 4 + 2][kk];
            float xv3 = sx[rg * 4 + 3][kk];
            acc[0].x = fmaf(xv0, wv.x, acc[0].x); acc[0].y = fmaf(xv0, wv.y, acc[0].y);
            acc[0].z = fmaf(xv0, wv.z, acc[0].z); acc[0].w = fmaf(xv0, wv.w, acc[0].w);
            acc[1].x = fmaf(xv1, wv.x, acc[1].x); acc[1].y = fmaf(xv1, wv.y, acc[1].y);
            acc[1].z = fmaf(xv1, wv.z, acc[1].z); acc[1].w = fmaf(xv1, wv.w, acc[1].w);
            acc[2].x = fmaf(xv2, wv.x, acc[2].x); acc[2].y = fmaf(xv2, wv.y, acc[2].y);
            acc[2].z = fmaf(xv2, wv.z, acc[2].z); acc[2].w = fmaf(xv2, wv.w, acc[2].w);
            acc[3].x = fmaf(xv3, wv.x, acc[3].x); acc[3].y = fmaf(xv3, wv.y, acc[3].y);
            acc[3].z = fmaf(xv3, wv.z, acc[3].z); acc[3].w = fmaf(xv3, wv.w, acc[3].w);
        }
    }

    float4 av = *(const float4*)(a + cgp * 4);
    float4 ad = *(const float4*)(a + H0 + cgp * 4);
#pragma unroll
    for (int ri = 0; ri < 4; ri++) {
        int grow = row0 + rg * 4 + ri;
        *(float4*)(g_Wh + ((size_t)r * N + grow) * H0 + cgp * 4) = acc[ri];
        float ps = acc[ri].x * av.x + acc[ri].y * av.y + acc[ri].z * av.z + acc[ri].w * av.w;
        float pd = acc[ri].x * ad.x + acc[ri].y * ad.y + acc[ri].z * ad.z + acc[ri].w * ad.w;
#pragma unroll
        for (int off = 8; off > 0; off >>= 1) {
            ps += __shfl_down_sync(0xffffffffu, ps, off, 16);
            pd += __shfl_down_sync(0xffffffffu, pd, off, 16);
        }
        if (cgp == 0) { g_ssrc[r * N + grow] = ps; g_sdst[r * N + grow] = pd; }
    }
}

__device__ void scan_body(int b, const float* __restrict__ adj) {
    int i = b & (N - 1);
    int r = b >> 12;
    int tid = threadIdx.x;
    int lane = tid & 31, wid = tid >> 5;
    __shared__ int s_wsum[8];

    const float4* row4 = (const float4*)(adj + ((size_t)r * N + i) * N);
    float4 v0 = row4[tid];
    float4 v1 = row4[tid + 256];
    float4 v2 = row4[tid + 512];
    float4 v3 = row4[tid + 768];
    unsigned mask = 0;
    if (v0.x > 0.f) mask |= 1u << 0;  if (v0.y > 0.f) mask |= 1u << 1;
    if (v0.z > 0.f) mask |= 1u << 2;  if (v0.w > 0.f) mask |= 1u << 3;
    if (v1.x > 0.f) mask |= 1u << 4;  if (v1.y > 0.f) mask |= 1u << 5;
    if (v1.z > 0.f) mask |= 1u << 6;  if (v1.w > 0.f) mask |= 1u << 7;
    if (v2.x > 0.f) mask |= 1u << 8;  if (v2.y > 0.f) mask |= 1u << 9;
    if (v2.z > 0.f) mask |= 1u << 10; if (v2.w > 0.f) mask |= 1u << 11;
    if (v3.x > 0.f) mask |= 1u << 12; if (v3.y > 0.f) mask |= 1u << 13;
    if (v3.z > 0.f) mask |= 1u << 14; if (v3.w > 0.f) mask |= 1u << 15;
    int c = __popc(mask);

    int pre = c;
#pragma unroll
    for (int off = 1; off < 32; off <<= 1) {
        int nv = __shfl_up_sync(0xffffffffu, pre, off);
        if (lane >= off) pre += nv;
    }
    if (lane == 31) s_wsum[wid] = pre;
    __syncthreads();
    int wbase = 0, total = 0;
#pragma unroll
    for (int w = 0; w < 8; w++) {
        int v = s_wsum[w];
        if (w < wid) wbase += v;
        total += v;
    }
    int pos = wbase + pre - c;

    int* gl = g_nbr_idx + ((size_t)(r * N + i)) * CAP;
    unsigned mm = mask;
    while (mm) {
        int bb = __ffs(mm) - 1;
        mm &= mm - 1;
        int q = bb >> 2, j = bb & 3;
        int col = ((tid + (q << 8)) << 2) + j;
        if (pos < CAP) gl[pos] = col;
        pos++;
    }
    if (tid == 0) g_nbr_cnt[r * N + i] = total;
}

__global__ void __launch_bounds__(256)
scan_wh_kernel(const float* __restrict__ x, const float* __restrict__ adj,
               const float* __restrict__ W1, const float* __restrict__ a1,
               const float* __restrict__ W2, const float* __restrict__ a2,
               const float* __restrict__ W3, const float* __restrict__ a3) {
    if (blockIdx.x < WH_BLOCKS)
        wh_body(blockIdx.x, x, W1, a1, W2, a2, W3, a3);
    else
        scan_body(blockIdx.x - WH_BLOCKS, adj);
}

// ================= kernel 2: softmax + Wh aggregation (warp per row,rel) ===
__global__ void __launch_bounds__(256)
attn2_kernel() {
    __shared__ float sw[8][CAP];
    __shared__ int   sidx[8][CAP];
    int tid = threadIdx.x;
    int lane = tid & 31, wid = tid >> 5;
    int id = blockIdx.x * 8 + wid;     // == r*N + i
    int r = id >> 12;

    int total = g_nbr_cnt[id];
    int cnt = min(total, CAP);
    const int* gl = g_nbr_idx + (size_t)id * CAP;
    float si = g_ssrc[id];
    for (int k = lane; k < cnt; k += 32) sidx[wid][k] = gl[k];
    __syncwarp();

    // pass 1: raw scores -> smem, running max
    float m = -FLT_MAX;
    for (int k = lane; k < cnt; k += 32) {
        float s = leaky(si + g_sdst[r * N + sidx[wid][k]]);
        sw[wid][k] = s;
        m = fmaxf(m, s);
    }
#pragma unroll
    for (int off = 16; off > 0; off >>= 1)
        m = fmaxf(m, __shfl_xor_sync(0xffffffffu, m, off));

    // pass 2: exp + sum
    float sum = 0.f;
    for (int k = lane; k < cnt; k += 32) {
        float e = expf(sw[wid][k] - m);
        sw[wid][k] = e;
        sum += e;
    }
#pragma unroll
    for (int off = 16; off > 0; off >>= 1)
        sum += __shfl_xor_sync(0xffffffffu, sum, off);
    float inv = 1.f / sum;
    __syncwarp();

    // gather: lane owns features (2lane, 2lane+1), MLP=4
    const float2* Wh2 = (const float2*)g_Wh + (size_t)r * N * 32;
    float2 a0 = {0.f, 0.f}, a1 = {0.f, 0.f}, a2 = {0.f, 0.f}, a3 = {0.f, 0.f};
    int k = 0;
    for (; k + 4 <= cnt; k += 4) {
        int4   jj = *(const int4*)&sidx[wid][k];
        float4 ww = *(const float4*)&sw[wid][k];
        float2 p0 = Wh2[(size_t)jj.x * 32 + lane];
        float2 p1 = Wh2[(size_t)jj.y * 32 + lane];
        float2 p2 = Wh2[(size_t)jj.z * 32 + lane];
        float2 p3 = Wh2[(size_t)jj.w * 32 + lane];
        a0.x = fmaf(ww.x, p0.x, a0.x); a0.y = fmaf(ww.x, p0.y, a0.y);
        a1.x = fmaf(ww.y, p1.x, a1.x); a1.y = fmaf(ww.y, p1.y, a1.y);
        a2.x = fmaf(ww.z, p2.x, a2.x); a2.y = fmaf(ww.z, p2.y, a2.y);
        a3.x = fmaf(ww.w, p3.x, a3.x); a3.y = fmaf(ww.w, p3.y, a3.y);
    }
    for (; k < cnt; k++) {
        int j = sidx[wid][k];
        float wk = sw[wid][k];
        float2 p = Wh2[(size_t)j * 32 + lane];
        a0.x = fmaf(wk, p.x, a0.x); a0.y = fmaf(wk, p.y, a0.y);
    }
    float2 o;
    o.x = (a0.x + a1.x + a2.x + a3.x) * inv;
    o.y = (a0.y + a1.y + a2.y + a3.y) * inv;
    *(float2*)(g_hr + (size_t)id * H0 + 2 * lane) = o;
}

// ================= kernel 3: fuse + support + Wg1 transpose ================
__global__ void __launch_bounds__(256)
fuse_kernel(const float* __restrict__ Wg0, const float* __restrict__ Wg1) {
    int tid = threadIdx.x;
    int rr = tid >> 6;
    int f = tid & 63;
    int i = blockIdx.x * 4 + rr;
    if (blockIdx.x == 0) {
#pragma unroll
        for (int t = tid; t < H1 * H2; t += 256) {
            int k = t >> 5, j = t & 31;
            g_Wg1T[j * H1 + k] = Wg1[t];
        }
    }
    __shared__ float hp[4][H0];
    float v = (g_hr[(size_t)i * H0 + f] +
               g_hr[((size_t)N + i) * H0 + f] +
               g_hr[((size_t)2 * N + i) * H0 + f]) * (1.f / 3.f);
    hp[rr][f] = 1.f / (1.f + expf(-v));
    __syncthreads();
    float acc = 0.f;
#pragma unroll 16
    for (int k = 0; k < H0; k++) acc = fmaf(hp[rr][k], Wg0[k * H1 + f], acc);
    g_support[(size_t)i * H1 + f] = acc;
}

__device__ __forceinline__ int read_relation(const void* p) {
    int r = *reinterpret_cast<const int*>(p);
    if (r < 0 || r > 2) {
        float fv = *reinterpret_cast<const float*>(p);
        r = (int)fv;
        if (r < 0 || r > 2) r = 0;
    }
    return r;
}

// ================= kernel 4: gnn layer 1 (1 warp/row, MLP=8) ==============
__global__ void __launch_bounds__(256)
gnn1_kernel(const float* __restrict__ bg0,
            const float* __restrict__ Wr,
            const float* __restrict__ br,
            const void* __restrict__ relation) {
    __shared__ int   sidx[8][CAP];
    __shared__ float shp[8][H1];
    int tid = threadIdx.x;
    int lane = tid & 31, wid = tid >> 5;
    int i = blockIdx.x * 8 + wid;
    int r = read_relation(relation);
    int rowid = r * N + i;
    int total = g_nbr_cnt[rowid];
    int cnt = min(total, CAP);
    const int* gl = g_nbr_idx + (size_t)rowid * CAP;
    for (int k = lane; k < cnt; k += 32) sidx[wid][k] = gl[k];
    __syncwarp();

    const float2* sup = (const float2*)g_support;
    float2 a0 = {0.f, 0.f}, a1 = {0.f, 0.f}, a2 = {0.f, 0.f}, a3 = {0.f, 0.f};
    float2 a4 = {0.f, 0.f}, a5 = {0.f, 0.f}, a6 = {0.f, 0.f}, a7 = {0.f, 0.f};
    int k = 0;
    for (; k + 8 <= cnt; k += 8) {
        int4 j0 = *(const int4*)&sidx[wid][k];
        int4 j1 = *(const int4*)&sidx[wid][k + 4];
        float2 p0 = sup[(size_t)j0.x * 32 + lane];
        float2 p1 = sup[(size_t)j0.y * 32 + lane];
        float2 p2 = sup[(size_t)j0.z * 32 + lane];
        float2 p3 = sup[(size_t)j0.w * 32 + lane];
        float2 p4 = sup[(size_t)j1.x * 32 + lane];
        float2 p5 = sup[(size_t)j1.y * 32 + lane];
        float2 p6 = sup[(size_t)j1.z * 32 + lane];
        float2 p7 = sup[(size_t)j1.w * 32 + lane];
        a0.x += p0.x; a0.y += p0.y;  a1.x += p1.x; a1.y += p1.y;
        a2.x += p2.x; a2.y += p2.y;  a3.x += p3.x; a3.y += p3.y;
        a4.x += p4.x; a4.y += p4.y;  a5.x += p5.x; a5.y += p5.y;
        a6.x += p6.x; a6.y += p6.y;  a7.x += p7.x; a7.y += p7.y;
    }
    for (; k + 4 <= cnt; k += 4) {
        int4 j0 = *(const int4*)&sidx[wid][k];
        float2 p0 = sup[(size_t)j0.x * 32 + lane];
        float2 p1 = sup[(size_t)j0.y * 32 + lane];
        float2 p2 = sup[(size_t)j0.z * 32 + lane];
        float2 p3 = sup[(size_t)j0.w * 32 + lane];
        a0.x += p0.x; a0.y += p0.y;  a1.x += p1.x; a1.y += p1.y;
        a2.x += p2.x; a2.y += p2.y;  a3.x += p3.x; a3.y += p3.y;
    }
    for (; k < cnt; k++) {
        float2 p = sup[(size_t)sidx[wid][k] * 32 + lane];
        a0.x += p.x; a0.y += p.y;
    }
    float dinv = 1.f / (float)total;
    float2 bg = ((const float2*)bg0)[lane];
    float2 h;
    h.x = leaky((a0.x + a1.x + a2.x + a3.x + a4.x + a5.x + a6.x + a7.x) * dinv + bg.x);
    h.y = leaky((a0.y + a1.y + a2.y + a3.y + a4.y + a5.y + a6.y + a7.y) * dinv + bg.y);
    *(float2*)&shp[wid][2 * lane] = h;
    __syncwarp();

    // epilogue: s2[lane] (Wg1T) and resid[lane] (Wr), vectorized over k
    float s2 = 0.f, rr2 = 0.f;
    const float4* wg = (const float4*)(g_Wg1T + lane * H1);
    const float4* wr = (const float4*)(Wr + lane * H1);
    const float4* hp4 = (const float4*)&shp[wid][0];
#pragma unroll
    for (int k4 = 0; k4 < H1 / 4; k4++) {
        float4 hv = hp4[k4];
        float4 g = wg[k4];
        float4 rv = wr[k4];
        s2  = fmaf(hv.x, g.x,  fmaf(hv.y, g.y,  fmaf(hv.z, g.z,  fmaf(hv.w, g.w,  s2))));
        rr2 = fmaf(hv.x, rv.x, fmaf(hv.y, rv.y, fmaf(hv.z, rv.z, fmaf(hv.w, rv.w, rr2))));
    }
    g_support2[(size_t)i * H2 + lane] = s2;
    g_resid[(size_t)i * H2 + lane]    = rr2 + br[lane];
}

// ================= kernel 5: gnn layer 2 + residual -> out (MLP=8) ========
__global__ void __launch_bounds__(256)
gnn2_kernel(const float* __restrict__ bg1,
            const void* __restrict__ relation,
            float* __restrict__ out) {
    __shared__ int sidx[8][CAP];
    int tid = threadIdx.x;
    int lane = tid & 31, wid = tid >> 5;
    int i = blockIdx.x * 8 + wid;
    int r = read_relation(relation);
    int rowid = r * N + i;
    int total = g_nbr_cnt[rowid];
    int cnt = min(total, CAP);
    const int* gl = g_nbr_idx + (size_t)rowid * CAP;
    for (int k = lane; k < cnt; k += 32) sidx[wid][k] = gl[k];
    __syncwarp();

    const float* sup2 = g_support2;
    float a0 = 0.f, a1 = 0.f, a2 = 0.f, a3 = 0.f;
    float a4 = 0.f, a5 = 0.f, a6 = 0.f, a7 = 0.f;
    int k = 0;
    for (; k + 8 <= cnt; k += 8) {
        int4 j0 = *(const int4*)&sidx[wid][k];
        int4 j1 = *(const int4*)&sidx[wid][k + 4];
        a0 += sup2[(size_t)j0.x * H2 + lane];
        a1 += sup2[(size_t)j0.y * H2 + lane];
        a2 += sup2[(size_t)j0.z * H2 + lane];
        a3 += sup2[(size_t)j0.w * H2 + lane];
        a4 += sup2[(size_t)j1.x * H2 + lane];
        a5 += sup2[(size_t)j1.y * H2 + lane];
        a6 += sup2[(size_t)j1.z * H2 + lane];
        a7 += sup2[(size_t)j1.w * H2 + lane];
    }
    for (; k + 4 <= cnt; k += 4) {
        int4 j0 = *(const int4*)&sidx[wid][k];
        a0 += sup2[(size_t)j0.x * H2 + lane];
        a1 += sup2[(size_t)j0.y * H2 + lane];
        a2 += sup2[(size_t)j0.z * H2 + lane];
        a3 += sup2[(size_t)j0.w * H2 + lane];
    }
    for (; k < cnt; k++) a0 += sup2[(size_t)sidx[wid][k] * H2 + lane];

    float agg = a0 + a1 + a2 + a3 + a4 + a5 + a6 + a7;
    float v = leaky(agg * (1.f / (float)total) + bg1[lane]);
    out[(size_t)i * H2 + lane] = v + g_resid[(size_t)i * H2 + lane];
}

extern "C" void kernel_launch(void* const* d_in, const int* in_sizes, int n_in,
                              void* d_out, int out_size) {
    const float* x   = (const float*)d_in[0];
    const float* adj = (const float*)d_in[1];
    const float* W1  = (const float*)d_in[2];
    const float* a1  = (const float*)d_in[3];
    const float* W2  = (const float*)d_in[4];
    const float* a2  = (const float*)d_in[5];
    const float* W3  = (const float*)d_in[6];
    const float* a3  = (const float*)d_in[7];
    const float* Wg0 = (const float*)d_in[8];
    const float* bg0 = (const float*)d_in[9];
    const float* Wg1 = (const float*)d_in[10];
    const float* bg1 = (const float*)d_in[11];
    const float* Wr  = (const float*)d_in[12];
    const float* br  = (const float*)d_in[13];
    const void*  rel = d_in[14];
    float* out = (float*)d_out;

    scan_wh_kernel<<<WH_BLOCKS + 3 * N, 256>>>(x, adj, W1, a1, W2, a2, W3, a3);
    attn2_kernel<<<3 * N / 8, 256>>>();
    fuse_kernel<<<N / 4, 256>>>(Wg0, Wg1);
    gnn1_kernel<<<N / 8, 256>>>(bg0, Wr, br, rel);
    gnn2_kernel<<<N / 8, 256>>>(bg1, rel, out);
}

// round 7
// speedup vs baseline: 1.1105x; 1.1105x over previous
#include <cuda_runtime.h>
#include <math.h>
#include <float.h>

#define N 4096
#define IN_F 256
#define H0 64
#define H1 64
#define H2 32
#define CAP 256
#define SLOPE 0.01f
#define WH_BLOCKS 192   // 64 row-tiles x 3 relations

// -------- scratch (device globals; no allocation) --------
__device__ int   g_nbr_idx[3 * N * CAP];
__device__ int   g_nbr_cnt[3 * N];
__device__ float g_Wh[3 * N * H0];
__device__ float g_ssrc[3 * N];
__device__ float g_sdst[3 * N];
__device__ float g_hr[3 * N * H0];
__device__ float g_support[N * H1];
__device__ float g_support2[N * H2];
__device__ float g_resid[N * H2];
__device__ float g_WrT[H1 * H2];   // Wr transposed to [k][j] (64 x 32)

__device__ __forceinline__ float leaky(float v) { return v >= 0.f ? v : SLOPE * v; }

// ================= merged kernel 1: wh tiles + adj scan ===================
__device__ void wh_body(int b,
                        const float* __restrict__ x,
                        const float* __restrict__ W1, const float* __restrict__ a1,
                        const float* __restrict__ W2, const float* __restrict__ a2,
                        const float* __restrict__ W3, const float* __restrict__ a3) {
    int r = b >> 6;
    int row0 = (b & 63) * 64;
    const float* W = (r == 0) ? W1 : (r == 1) ? W2 : W3;
    const float* a = (r == 0) ? a1 : (r == 1) ? a2 : a3;
    int tid = threadIdx.x;
    int rg = tid >> 4;
    int cgp = tid & 15;

    __shared__ float sx[64][64];
    __shared__ float sW[64][64];

    float4 acc[4];
#pragma unroll
    for (int q = 0; q < 4; q++) acc[q] = make_float4(0.f, 0.f, 0.f, 0.f);

    for (int k0 = 0; k0 < IN_F; k0 += 64) {
        __syncthreads();
#pragma unroll
        for (int q = 0; q < 4; q++) {
            int lin = tid + q * 256;
            int rr = lin >> 4, c4 = (lin & 15) << 2;
            *(float4*)&sx[rr][c4] = *(const float4*)(x + (size_t)(row0 + rr) * IN_F + k0 + c4);
        }
#pragma unroll
        for (int q = 0; q < 4; q++) {
            int lin = tid + q * 256;
            int kr = lin >> 4, c4 = (lin & 15) << 2;
            *(float4*)&sW[kr][c4] = *(const float4*)(W + (size_t)(k0 + kr) * H0 + c4);
        }
        __syncthreads();
#pragma unroll 16
        for (int kk = 0; kk < 64; kk++) {
            float4 wv = *(float4*)&sW[kk][cgp * 4];
            float xv0 = sx[rg * 4 + 0][kk];
            float xv1 = sx[rg * 4 + 1][kk];
            float xv2 = sx[rg * 4 + 2][kk];
            float xv3 = sx[rg * 4 + 3][kk];
            acc[0].x = fmaf(xv0, wv.x, acc[0].x); acc[0].y = fmaf(xv0, wv.y, acc[0].y);
            acc[0].z = fmaf(xv0, wv.z, acc[0].z); acc[0].w = fmaf(xv0, wv.w, acc[0].w);
            acc[1].x = fmaf(xv1, wv.x, acc[1].x); acc[1].y = fmaf(xv1, wv.y, acc[1].y);
            acc[1].z = fmaf(xv1, wv.z, acc[1].z); acc[1].w = fmaf(xv1, wv.w, acc[1].w);
            acc[2].x = fmaf(xv2, wv.x, acc[2].x); acc[2].y = fmaf(xv2, wv.y, acc[2].y);
            acc[2].z = fmaf(xv2, wv.z, acc[2].z); acc[2].w = fmaf(xv2, wv.w, acc[2].w);
            acc[3].x = fmaf(xv3, wv.x, acc[3].x); acc[3].y = fmaf(xv3, wv.y, acc[3].y);
            acc[3].z = fmaf(xv3, wv.z, acc[3].z); acc[3].w = fmaf(xv3, wv.w, acc[3].w);
        }
    }

    float4 av = *(const float4*)(a + cgp * 4);
    float4 ad = *(const float4*)(a + H0 + cgp * 4);
#pragma unroll
    for (int ri = 0; ri < 4; ri++) {
        int grow = row0 + rg * 4 + ri;
        *(float4*)(g_Wh + ((size_t)r * N + grow) * H0 + cgp * 4) = acc[ri];
        float ps = acc[ri].x * av.x + acc[ri].y * av.y + acc[ri].z * av.z + acc[ri].w * av.w;
        float pd = acc[ri].x * ad.x + acc[ri].y * ad.y + acc[ri].z * ad.z + acc[ri].w * ad.w;
#pragma unroll
        for (int off = 8; off > 0; off >>= 1) {
            ps += __shfl_down_sync(0xffffffffu, ps, off, 16);
            pd += __shfl_down_sync(0xffffffffu, pd, off, 16);
        }
        if (cgp == 0) { g_ssrc[r * N + grow] = ps; g_sdst[r * N + grow] = pd; }
    }
}

__device__ void scan_body(int b, const float* __restrict__ adj) {
    int i = b & (N - 1);
    int r = b >> 12;
    int tid = threadIdx.x;
    int lane = tid & 31, wid = tid >> 5;
    __shared__ int s_wsum[8];

    const float4* row4 = (const float4*)(adj + ((size_t)r * N + i) * N);
    float4 v0 = row4[tid];
    float4 v1 = row4[tid + 256];
    float4 v2 = row4[tid + 512];
    float4 v3 = row4[tid + 768];
    unsigned mask = 0;
    if (v0.x > 0.f) mask |= 1u << 0;  if (v0.y > 0.f) mask |= 1u << 1;
    if (v0.z > 0.f) mask |= 1u << 2;  if (v0.w > 0.f) mask |= 1u << 3;
    if (v1.x > 0.f) mask |= 1u << 4;  if (v1.y > 0.f) mask |= 1u << 5;
    if (v1.z > 0.f) mask |= 1u << 6;  if (v1.w > 0.f) mask |= 1u << 7;
    if (v2.x > 0.f) mask |= 1u << 8;  if (v2.y > 0.f) mask |= 1u << 9;
    if (v2.z > 0.f) mask |= 1u << 10; if (v2.w > 0.f) mask |= 1u << 11;
    if (v3.x > 0.f) mask |= 1u << 12; if (v3.y > 0.f) mask |= 1u << 13;
    if (v3.z > 0.f) mask |= 1u << 14; if (v3.w > 0.f) mask |= 1u << 15;
    int c = __popc(mask);

    int pre = c;
#pragma unroll
    for (int off = 1; off < 32; off <<= 1) {
        int nv = __shfl_up_sync(0xffffffffu, pre, off);
        if (lane >= off) pre += nv;
    }
    if (lane == 31) s_wsum[wid] = pre;
    __syncthreads();
    int wbase = 0, total = 0;
#pragma unroll
    for (int w = 0; w < 8; w++) {
        int v = s_wsum[w];
        if (w < wid) wbase += v;
        total += v;
    }
    int pos = wbase + pre - c;

    int* gl = g_nbr_idx + ((size_t)(r * N + i)) * CAP;
    unsigned mm = mask;
    while (mm) {
        int bb = __ffs(mm) - 1;
        mm &= mm - 1;
        int q = bb >> 2, j = bb & 3;
        int col = ((tid + (q << 8)) << 2) + j;
        if (pos < CAP) gl[pos] = col;
        pos++;
    }
    if (tid == 0) g_nbr_cnt[r * N + i] = total;
}

__global__ void __launch_bounds__(256)
scan_wh_kernel(const float* __restrict__ x, const float* __restrict__ adj,
               const float* __restrict__ W1, const float* __restrict__ a1,
               const float* __restrict__ W2, const float* __restrict__ a2,
               const float* __restrict__ W3, const float* __restrict__ a3) {
    if (blockIdx.x < WH_BLOCKS)
        wh_body(blockIdx.x, x, W1, a1, W2, a2, W3, a3);
    else
        scan_body(blockIdx.x - WH_BLOCKS, adj);
}

// ================= kernel 2: softmax + Wh aggregation (warp per row,rel) ===
__global__ void __launch_bounds__(256)
attn2_kernel() {
    __shared__ float sw[8][CAP];
    __shared__ int   sidx[8][CAP];
    int tid = threadIdx.x;
    int lane = tid & 31, wid = tid >> 5;
    int id = blockIdx.x * 8 + wid;     // == r*N + i
    int r = id >> 12;

    int total = g_nbr_cnt[id];
    int cnt = min(total, CAP);
    const int* gl = g_nbr_idx + (size_t)id * CAP;
    float si = g_ssrc[id];
    for (int k = lane; k < cnt; k += 32) sidx[wid][k] = gl[k];
    __syncwarp();

    // pass 1: raw scores -> smem, running max
    float m = -FLT_MAX;
    for (int k = lane; k < cnt; k += 32) {
        float s = leaky(si + g_sdst[r * N + sidx[wid][k]]);
        sw[wid][k] = s;
        m = fmaxf(m, s);
    }
#pragma unroll
    for (int off = 16; off > 0; off >>= 1)
        m = fmaxf(m, __shfl_xor_sync(0xffffffffu, m, off));

    // pass 2: exp + sum
    float sum = 0.f;
    for (int k = lane; k < cnt; k += 32) {
        float e = expf(sw[wid][k] - m);
        sw[wid][k] = e;
        sum += e;
    }
#pragma unroll
    for (int off = 16; off > 0; off >>= 1)
        sum += __shfl_xor_sync(0xffffffffu, sum, off);
    float inv = 1.f / sum;
    __syncwarp();

    // weighted gather: lane owns features (2lane, 2lane+1), MLP=8
    const float2* Wh2 = (const float2*)g_Wh + (size_t)r * N * 32;
    float2 a0 = {0.f, 0.f}, a1 = {0.f, 0.f}, a2 = {0.f, 0.f}, a3 = {0.f, 0.f};
    float2 a4 = {0.f, 0.f}, a5 = {0.f, 0.f}, a6 = {0.f, 0.f}, a7 = {0.f, 0.f};
    int k = 0;
    for (; k + 8 <= cnt; k += 8) {
        int4   j0 = *(const int4*)&sidx[wid][k];
        int4   j1 = *(const int4*)&sidx[wid][k + 4];
        float4 w0 = *(const float4*)&sw[wid][k];
        float4 w1 = *(const float4*)&sw[wid][k + 4];
        float2 p0 = Wh2[(size_t)j0.x * 32 + lane];
        float2 p1 = Wh2[(size_t)j0.y * 32 + lane];
        float2 p2 = Wh2[(size_t)j0.z * 32 + lane];
        float2 p3 = Wh2[(size_t)j0.w * 32 + lane];
        float2 p4 = Wh2[(size_t)j1.x * 32 + lane];
        float2 p5 = Wh2[(size_t)j1.y * 32 + lane];
        float2 p6 = Wh2[(size_t)j1.z * 32 + lane];
        float2 p7 = Wh2[(size_t)j1.w * 32 + lane];
        a0.x = fmaf(w0.x, p0.x, a0.x); a0.y = fmaf(w0.x, p0.y, a0.y);
        a1.x = fmaf(w0.y, p1.x, a1.x); a1.y = fmaf(w0.y, p1.y, a1.y);
        a2.x = fmaf(w0.z, p2.x, a2.x); a2.y = fmaf(w0.z, p2.y, a2.y);
        a3.x = fmaf(w0.w, p3.x, a3.x); a3.y = fmaf(w0.w, p3.y, a3.y);
        a4.x = fmaf(w1.x, p4.x, a4.x); a4.y = fmaf(w1.x, p4.y, a4.y);
        a5.x = fmaf(w1.y, p5.x, a5.x); a5.y = fmaf(w1.y, p5.y, a5.y);
        a6.x = fmaf(w1.z, p6.x, a6.x); a6.y = fmaf(w1.z, p6.y, a6.y);
        a7.x = fmaf(w1.w, p7.x, a7.x); a7.y = fmaf(w1.w, p7.y, a7.y);
    }
    for (; k + 4 <= cnt; k += 4) {
        int4   jj = *(const int4*)&sidx[wid][k];
        float4 ww = *(const float4*)&sw[wid][k];
        float2 p0 = Wh2[(size_t)jj.x * 32 + lane];
        float2 p1 = Wh2[(size_t)jj.y * 32 + lane];
        float2 p2 = Wh2[(size_t)jj.z * 32 + lane];
        float2 p3 = Wh2[(size_t)jj.w * 32 + lane];
        a0.x = fmaf(ww.x, p0.x, a0.x); a0.y = fmaf(ww.x, p0.y, a0.y);
        a1.x = fmaf(ww.y, p1.x, a1.x); a1.y = fmaf(ww.y, p1.y, a1.y);
        a2.x = fmaf(ww.z, p2.x, a2.x); a2.y = fmaf(ww.z, p2.y, a2.y);
        a3.x = fmaf(ww.w, p3.x, a3.x); a3.y = fmaf(ww.w, p3.y, a3.y);
    }
    for (; k < cnt; k++) {
        int j = sidx[wid][k];
        float wk = sw[wid][k];
        float2 p = Wh2[(size_t)j * 32 + lane];
        a0.x = fmaf(wk, p.x, a0.x); a0.y = fmaf(wk, p.y, a0.y);
    }
    float2 o;
    o.x = (a0.x + a1.x + a2.x + a3.x + a4.x + a5.x + a6.x + a7.x) * inv;
    o.y = (a0.y + a1.y + a2.y + a3.y + a4.y + a5.y + a6.y + a7.y) * inv;
    *(float2*)(g_hr + (size_t)id * H0 + 2 * lane) = o;
}

// ================= kernel 3: fuse + support + Wr transpose ================
__global__ void __launch_bounds__(256)
fuse_kernel(const float* __restrict__ Wg0, const float* __restrict__ Wr) {
    int tid = threadIdx.x;
    int rr = tid >> 6;
    int f = tid & 63;
    int i = blockIdx.x * 4 + rr;
    if (blockIdx.x == 0) {
        // Wr is [H2][H1] row-major ([j][k]); build WrT[k][j]
#pragma unroll
        for (int t = tid; t < H1 * H2; t += 256) {
            int j = t >> 6, k = t & 63;
            g_WrT[k * H2 + j] = Wr[t];
        }
    }
    __shared__ float hp[4][H0];
    float v = (g_hr[(size_t)i * H0 + f] +
               g_hr[((size_t)N + i) * H0 + f] +
               g_hr[((size_t)2 * N + i) * H0 + f]) * (1.f / 3.f);
    hp[rr][f] = 1.f / (1.f + expf(-v));
    __syncthreads();
    float acc = 0.f;
#pragma unroll 16
    for (int k = 0; k < H0; k++) acc = fmaf(hp[rr][k], Wg0[k * H1 + f], acc);
    g_support[(size_t)i * H1 + f] = acc;
}

__device__ __forceinline__ int read_relation(const void* p) {
    int r = *reinterpret_cast<const int*>(p);
    if (r < 0 || r > 2) {
        float fv = *reinterpret_cast<const float*>(p);
        r = (int)fv;
        if (r < 0 || r > 2) r = 0;
    }
    return r;
}

// ================= kernel 4: gnn layer 1 (1 warp/row, MLP=8) ==============
__global__ void __launch_bounds__(256)
gnn1_kernel(const float* __restrict__ bg0,
            const float* __restrict__ Wg1,
            const float* __restrict__ br,
            const void* __restrict__ relation) {
    __shared__ int   sidx[8][CAP];
    __shared__ float shp[8][H1];
    int tid = threadIdx.x;
    int lane = tid & 31, wid = tid >> 5;
    int i = blockIdx.x * 8 + wid;
    int r = read_relation(relation);
    int rowid = r * N + i;
    int total = g_nbr_cnt[rowid];
    int cnt = min(total, CAP);
    const int* gl = g_nbr_idx + (size_t)rowid * CAP;
    for (int k = lane; k < cnt; k += 32) sidx[wid][k] = gl[k];
    __syncwarp();

    const float2* sup = (const float2*)g_support;
    float2 a0 = {0.f, 0.f}, a1 = {0.f, 0.f}, a2 = {0.f, 0.f}, a3 = {0.f, 0.f};
    float2 a4 = {0.f, 0.f}, a5 = {0.f, 0.f}, a6 = {0.f, 0.f}, a7 = {0.f, 0.f};
    int k = 0;
    for (; k + 8 <= cnt; k += 8) {
        int4 j0 = *(const int4*)&sidx[wid][k];
        int4 j1 = *(const int4*)&sidx[wid][k + 4];
        float2 p0 = sup[(size_t)j0.x * 32 + lane];
        float2 p1 = sup[(size_t)j0.y * 32 + lane];
        float2 p2 = sup[(size_t)j0.z * 32 + lane];
        float2 p3 = sup[(size_t)j0.w * 32 + lane];
        float2 p4 = sup[(size_t)j1.x * 32 + lane];
        float2 p5 = sup[(size_t)j1.y * 32 + lane];
        float2 p6 = sup[(size_t)j1.z * 32 + lane];
        float2 p7 = sup[(size_t)j1.w * 32 + lane];
        a0.x += p0.x; a0.y += p0.y;  a1.x += p1.x; a1.y += p1.y;
        a2.x += p2.x; a2.y += p2.y;  a3.x += p3.x; a3.y += p3.y;
        a4.x += p4.x; a4.y += p4.y;  a5.x += p5.x; a5.y += p5.y;
        a6.x += p6.x; a6.y += p6.y;  a7.x += p7.x; a7.y += p7.y;
    }
    for (; k + 4 <= cnt; k += 4) {
        int4 j0 = *(const int4*)&sidx[wid][k];
        float2 p0 = sup[(size_t)j0.x * 32 + lane];
        float2 p1 = sup[(size_t)j0.y * 32 + lane];
        float2 p2 = sup[(size_t)j0.z * 32 + lane];
        float2 p3 = sup[(size_t)j0.w * 32 + lane];
        a0.x += p0.x; a0.y += p0.y;  a1.x += p1.x; a1.y += p1.y;
        a2.x += p2.x; a2.y += p2.y;  a3.x += p3.x; a3.y += p3.y;
    }
    for (; k < cnt; k++) {
        float2 p = sup[(size_t)sidx[wid][k] * 32 + lane];
        a0.x += p.x; a0.y += p.y;
    }
    float dinv = 1.f / (float)total;
    float2 bg = ((const float2*)bg0)[lane];
    float2 h;
    h.x = leaky((a0.x + a1.x + a2.x + a3.x + a4.x + a5.x + a6.x + a7.x) * dinv + bg.x);
    h.y = leaky((a0.y + a1.y + a2.y + a3.y + a4.y + a5.y + a6.y + a7.y) * dinv + bg.y);
    *(float2*)&shp[wid][2 * lane] = h;
    __syncwarp();

    // epilogue: lane = output j; coalesced LDG on Wg1[k][j] and WrT[k][j]
    float s2 = 0.f, rr2 = 0.f;
#pragma unroll
    for (int kk = 0; kk < H1; kk += 4) {
        float h0 = shp[wid][kk + 0];
        float h1 = shp[wid][kk + 1];
        float h2 = shp[wid][kk + 2];
        float h3 = shp[wid][kk + 3];
        s2  = fmaf(h0, Wg1[(kk + 0) * H2 + lane], s2);
        s2  = fmaf(h1, Wg1[(kk + 1) * H2 + lane], s2);
        s2  = fmaf(h2, Wg1[(kk + 2) * H2 + lane], s2);
        s2  = fmaf(h3, Wg1[(kk + 3) * H2 + lane], s2);
        rr2 = fmaf(h0, g_WrT[(kk + 0) * H2 + lane], rr2);
        rr2 = fmaf(h1, g_WrT[(kk + 1) * H2 + lane], rr2);
        rr2 = fmaf(h2, g_WrT[(kk + 2) * H2 + lane], rr2);
        rr2 = fmaf(h3, g_WrT[(kk + 3) * H2 + lane], rr2);
    }
    g_support2[(size_t)i * H2 + lane] = s2;
    g_resid[(size_t)i * H2 + lane]    = rr2 + br[lane];
}

// ================= kernel 5: gnn layer 2 + residual -> out (MLP=8) ========
__global__ void __launch_bounds__(256)
gnn2_kernel(const float* __restrict__ bg1,
            const void* __restrict__ relation,
            float* __restrict__ out) {
    __shared__ int sidx[8][CAP];
    int tid = threadIdx.x;
    int lane = tid & 31, wid = tid >> 5;
    int i = blockIdx.x * 8 + wid;
    int r = read_relation(relation);
    int rowid = r * N + i;
    int total = g_nbr_cnt[rowid];
    int cnt = min(total, CAP);
    const int* gl = g_nbr_idx + (size_t)rowid * CAP;
    for (int k = lane; k < cnt; k += 32) sidx[wid][k] = gl[k];
    __syncwarp();

    const float* sup2 = g_support2;
    float a0 = 0.f, a1 = 0.f, a2 = 0.f, a3 = 0.f;
    float a4 = 0.f, a5 = 0.f, a6 = 0.f, a7 = 0.f;
    int k = 0;
    for (; k + 8 <= cnt; k += 8) {
        int4 j0 = *(const int4*)&sidx[wid][k];
        int4 j1 = *(const int4*)&sidx[wid][k + 4];
        a0 += sup2[(size_t)j0.x * H2 + lane];
        a1 += sup2[(size_t)j0.y * H2 + lane];
        a2 += sup2[(size_t)j0.z * H2 + lane];
        a3 += sup2[(size_t)j0.w * H2 + lane];
        a4 += sup2[(size_t)j1.x * H2 + lane];
        a5 += sup2[(size_t)j1.y * H2 + lane];
        a6 += sup2[(size_t)j1.z * H2 + lane];
        a7 += sup2[(size_t)j1.w * H2 + lane];
    }
    for (; k + 4 <= cnt; k += 4) {
        int4 j0 = *(const int4*)&sidx[wid][k];
        a0 += sup2[(size_t)j0.x * H2 + lane];
        a1 += sup2[(size_t)j0.y * H2 + lane];
        a2 += sup2[(size_t)j0.z * H2 + lane];
        a3 += sup2[(size_t)j0.w * H2 + lane];
    }
    for (; k < cnt; k++) a0 += sup2[(size_t)sidx[wid][k] * H2 + lane];

    float agg = a0 + a1 + a2 + a3 + a4 + a5 + a6 + a7;
    float v = leaky(agg * (1.f / (float)total) + bg1[lane]);
    out[(size_t)i * H2 + lane] = v + g_resid[(size_t)i * H2 + lane];
}

extern "C" void kernel_launch(void* const* d_in, const int* in_sizes, int n_in,
                              void* d_out, int out_size) {
    const float* x   = (const float*)d_in[0];
    const float* adj = (const float*)d_in[1];
    const float* W1  = (const float*)d_in[2];
    const float* a1  = (const float*)d_in[3];
    const float* W2  = (const float*)d_in[4];
    const float* a2  = (const float*)d_in[5];
    const float* W3  = (const float*)d_in[6];
    const float* a3  = (const float*)d_in[7];
    const float* Wg0 = (const float*)d_in[8];
    const float* bg0 = (const float*)d_in[9];
    const float* Wg1 = (const float*)d_in[10];
    const float* bg1 = (const float*)d_in[11];
    const float* Wr  = (const float*)d_in[12];
    const float* br  = (const float*)d_in[13];
    const void*  rel = d_in[14];
    float* out = (float*)d_out;

    scan_wh_kernel<<<WH_BLOCKS + 3 * N, 256>>>(x, adj, W1, a1, W2, a2, W3, a3);
    attn2_kernel<<<3 * N / 8, 256>>>();
    fuse_kernel<<<N / 4, 256>>>(Wg0, Wr);
    gnn1_kernel<<<N / 8, 256>>>(bg0, Wg1, br, rel);
    gnn2_kernel<<<N / 8, 256>>>(bg1, rel, out);
}

// round 8
// speedup vs baseline: 1.1574x; 1.0423x over previous
#include <cuda_runtime.h>
#include <math.h>
#include <float.h>

#define N 4096
#define IN_F 256
#define H0 64
#define H1 64
#define H2 32
#define CAP 256
#define SLOPE 0.01f

// -------- scratch (device globals; no allocation) --------
__device__ int    g_nbr_idx[N * CAP];     // only the selected relation
__device__ int    g_nbr_cnt[N];
__device__ float  g_Wh[3 * N * H0];
__device__ float  g_ssrc[3 * N];
__device__ float  g_sdst[3 * N];
__device__ float  g_hr[3 * N * H0];
__device__ float  g_support[N * H1];
__device__ float  g_support2[N * H2];
__device__ float  g_resid[N * H2];
__device__ float2 g_WgC[H1 * H2];          // {Wg1[k][j], Wr[j][k]} combined

__device__ __forceinline__ float leaky(float v) { return v >= 0.f ? v : SLOPE * v; }

__device__ __forceinline__ int read_relation(const void* p) {
    int r = *reinterpret_cast<const int*>(p);
    if (r < 0 || r > 2) {
        float fv = *reinterpret_cast<const float*>(p);
        r = (int)fv;
        if (r < 0 || r > 2) r = 0;
    }
    return r;
}

// ================= kernel 1: Wh = x @ W_r, s_src, s_dst ===================
// grid (64, 3), 256 threads. 64x64 tile, 4x4 register tile per thread.
__global__ void __launch_bounds__(256)
wh_kernel(const float* __restrict__ x,
          const float* __restrict__ W1, const float* __restrict__ a1,
          const float* __restrict__ W2, const float* __restrict__ a2,
          const float* __restrict__ W3, const float* __restrict__ a3) {
    int r = blockIdx.y;
    int row0 = blockIdx.x * 64;
    const float* W = (r == 0) ? W1 : (r == 1) ? W2 : W3;
    const float* a = (r == 0) ? a1 : (r == 1) ? a2 : a3;
    int tid = threadIdx.x;
    int rg = tid >> 4;
    int cgp = tid & 15;

    __shared__ float sx[64][64];
    __shared__ float sW[64][64];

    float4 acc[4];
#pragma unroll
    for (int q = 0; q < 4; q++) acc[q] = make_float4(0.f, 0.f, 0.f, 0.f);

    for (int k0 = 0; k0 < IN_F; k0 += 64) {
        __syncthreads();
#pragma unroll
        for (int q = 0; q < 4; q++) {
            int lin = tid + q * 256;
            int rr = lin >> 4, c4 = (lin & 15) << 2;
            *(float4*)&sx[rr][c4] = *(const float4*)(x + (size_t)(row0 + rr) * IN_F + k0 + c4);
        }
#pragma unroll
        for (int q = 0; q < 4; q++) {
            int lin = tid + q * 256;
            int kr = lin >> 4, c4 = (lin & 15) << 2;
            *(float4*)&sW[kr][c4] = *(const float4*)(W + (size_t)(k0 + kr) * H0 + c4);
        }
        __syncthreads();
#pragma unroll 16
        for (int kk = 0; kk < 64; kk++) {
            float4 wv = *(float4*)&sW[kk][cgp * 4];
            float xv0 = sx[rg * 4 + 0][kk];
            float xv1 = sx[rg * 4 + 1][kk];
            float xv2 = sx[rg * 4 + 2][kk];
            float xv3 = sx[rg * 4 + 3][kk];
            acc[0].x = fmaf(xv0, wv.x, acc[0].x); acc[0].y = fmaf(xv0, wv.y, acc[0].y);
            acc[0].z = fmaf(xv0, wv.z, acc[0].z); acc[0].w = fmaf(xv0, wv.w, acc[0].w);
            acc[1].x = fmaf(xv1, wv.x, acc[1].x); acc[1].y = fmaf(xv1, wv.y, acc[1].y);
            acc[1].z = fmaf(xv1, wv.z, acc[1].z); acc[1].w = fmaf(xv1, wv.w, acc[1].w);
            acc[2].x = fmaf(xv2, wv.x, acc[2].x); acc[2].y = fmaf(xv2, wv.y, acc[2].y);
            acc[2].z = fmaf(xv2, wv.z, acc[2].z); acc[2].w = fmaf(xv2, wv.w, acc[2].w);
            acc[3].x = fmaf(xv3, wv.x, acc[3].x); acc[3].y = fmaf(xv3, wv.y, acc[3].y);
            acc[3].z = fmaf(xv3, wv.z, acc[3].z); acc[3].w = fmaf(xv3, wv.w, acc[3].w);
        }
    }

    float4 av = *(const float4*)(a + cgp * 4);
    float4 ad = *(const float4*)(a + H0 + cgp * 4);
#pragma unroll
    for (int ri = 0; ri < 4; ri++) {
        int grow = row0 + rg * 4 + ri;
        *(float4*)(g_Wh + ((size_t)r * N + grow) * H0 + cgp * 4) = acc[ri];
        float ps = acc[ri].x * av.x + acc[ri].y * av.y + acc[ri].z * av.z + acc[ri].w * av.w;
        float pd = acc[ri].x * ad.x + acc[ri].y * ad.y + acc[ri].z * ad.z + acc[ri].w * ad.w;
#pragma unroll
        for (int off = 8; off > 0; off >>= 1) {
            ps += __shfl_down_sync(0xffffffffu, ps, off, 16);
            pd += __shfl_down_sync(0xffffffffu, pd, off, 16);
        }
        if (cgp == 0) { g_ssrc[r * N + grow] = ps; g_sdst[r * N + grow] = pd; }
    }
}

// ===== kernel 2: adj scan + softmax + Wh aggregation, fully fused =========
// grid 3*N, 256 threads. One block per (relation, row). Gathers hide
// under the HBM adjacency stream of co-resident blocks.
__global__ void __launch_bounds__(256)
scan_attn_kernel(const float* __restrict__ adj, const void* __restrict__ relation) {
    __shared__ int   s_idx[CAP];
    __shared__ float s_w[CAP];
    __shared__ int   s_wsum[8];
    __shared__ float s_m[8];
    __shared__ float s_s[8];
    __shared__ float s_acc[4][H0];

    int b = blockIdx.x;
    int i = b & (N - 1);
    int r = b >> 12;
    int id = r * N + i;
    int tid = threadIdx.x;
    int lane = tid & 31, wid = tid >> 5;

    // --- coalesced adjacency row scan
    const float4* row4 = (const float4*)(adj + (size_t)id * N);
    float4 v0 = row4[tid];
    float4 v1 = row4[tid + 256];
    float4 v2 = row4[tid + 512];
    float4 v3 = row4[tid + 768];
    unsigned mask = 0;
    if (v0.x > 0.f) mask |= 1u << 0;  if (v0.y > 0.f) mask |= 1u << 1;
    if (v0.z > 0.f) mask |= 1u << 2;  if (v0.w > 0.f) mask |= 1u << 3;
    if (v1.x > 0.f) mask |= 1u << 4;  if (v1.y > 0.f) mask |= 1u << 5;
    if (v1.z > 0.f) mask |= 1u << 6;  if (v1.w > 0.f) mask |= 1u << 7;
    if (v2.x > 0.f) mask |= 1u << 8;  if (v2.y > 0.f) mask |= 1u << 9;
    if (v2.z > 0.f) mask |= 1u << 10; if (v2.w > 0.f) mask |= 1u << 11;
    if (v3.x > 0.f) mask |= 1u << 12; if (v3.y > 0.f) mask |= 1u << 13;
    if (v3.z > 0.f) mask |= 1u << 14; if (v3.w > 0.f) mask |= 1u << 15;
    int c = __popc(mask);

    int pre = c;
#pragma unroll
    for (int off = 1; off < 32; off <<= 1) {
        int nv = __shfl_up_sync(0xffffffffu, pre, off);
        if (lane >= off) pre += nv;
    }
    if (lane == 31) s_wsum[wid] = pre;
    __syncthreads();
    int wbase = 0, total = 0;
#pragma unroll
    for (int w = 0; w < 8; w++) {
        int v = s_wsum[w];
        if (w < wid) wbase += v;
        total += v;
    }
    int pos = wbase + pre - c;

    unsigned mm = mask;
    while (mm) {
        int bb = __ffs(mm) - 1;
        mm &= mm - 1;
        int q = bb >> 2, j = bb & 3;
        int col = ((tid + (q << 8)) << 2) + j;
        if (pos < CAP) s_idx[pos] = col;
        pos++;
    }
    __syncthreads();
    int cnt = min(total, CAP);

    // persist list only for the relation the GNN layers use
    int relv = read_relation(relation);
    if (r == relv) {
        int* gl = g_nbr_idx + (size_t)i * CAP;
        for (int k = tid; k < cnt; k += 256) gl[k] = s_idx[k];
        if (tid == 0) g_nbr_cnt[i] = total;
    }

    // --- scores (one element per thread; cnt <= 256)
    float sc = -FLT_MAX;
    if (tid < cnt) sc = leaky(g_ssrc[id] + g_sdst[r * N + s_idx[tid]]);

    float m = sc;
#pragma unroll
    for (int off = 16; off > 0; off >>= 1)
        m = fmaxf(m, __shfl_xor_sync(0xffffffffu, m, off));
    if (lane == 0) s_m[wid] = m;
    __syncthreads();
    float bm = s_m[0];
#pragma unroll
    for (int w = 1; w < 8; w++) bm = fmaxf(bm, s_m[w]);

    float e = (tid < cnt) ? expf(sc - bm) : 0.f;
    s_w[tid] = e;
    float sum = e;
#pragma unroll
    for (int off = 16; off > 0; off >>= 1)
        sum += __shfl_xor_sync(0xffffffffu, sum, off);
    if (lane == 0) s_s[wid] = sum;
    __syncthreads();
    float bs = s_s[0];
#pragma unroll
    for (int w = 1; w < 8; w++) bs += s_s[w];
    float inv = 1.f / bs;

    // --- weighted gather: 4 k-chunks x 64 features, MLP=4 per chunk
    int f = tid & 63;
    int kc = tid >> 6;
    const float* WhR = g_Wh + (size_t)r * N * H0;
    float acc = 0.f;
    int k = kc;
    for (; k + 12 < cnt; k += 16) {
        int j0 = s_idx[k], j1 = s_idx[k + 4], j2 = s_idx[k + 8], j3 = s_idx[k + 12];
        float w0 = s_w[k], w1 = s_w[k + 4], w2 = s_w[k + 8], w3 = s_w[k + 12];
        float p0 = WhR[(size_t)j0 * H0 + f];
        float p1 = WhR[(size_t)j1 * H0 + f];
        float p2 = WhR[(size_t)j2 * H0 + f];
        float p3 = WhR[(size_t)j3 * H0 + f];
        acc = fmaf(w0, p0, acc);
        acc = fmaf(w1, p1, acc);
        acc = fmaf(w2, p2, acc);
        acc = fmaf(w3, p3, acc);
    }
    for (; k < cnt; k += 4)
        acc = fmaf(s_w[k], WhR[(size_t)s_idx[k] * H0 + f], acc);
    s_acc[kc][f] = acc;
    __syncthreads();
    if (tid < H0) {
        float o = (s_acc[0][tid] + s_acc[1][tid] + s_acc[2][tid] + s_acc[3][tid]) * inv;
        g_hr[(size_t)id * H0 + tid] = o;
    }
}

// ================= kernel 3: fuse + support + combined-weight prep ========
__global__ void __launch_bounds__(256)
fuse_kernel(const float* __restrict__ Wg0, const float* __restrict__ Wg1,
            const float* __restrict__ Wr) {
    int tid = threadIdx.x;
    int rr = tid >> 6;
    int f = tid & 63;
    int i = blockIdx.x * 4 + rr;
    if (blockIdx.x == 0) {
        // WgC[k*32+j] = { Wg1[k][j], Wr[j][k] }
#pragma unroll
        for (int t = tid; t < H1 * H2; t += 256) {
            int k = t >> 5, j = t & 31;
            g_WgC[t] = make_float2(Wg1[k * H2 + j], Wr[j * H1 + k]);
        }
    }
    __shared__ float hp[4][H0];
    float v = (g_hr[(size_t)i * H0 + f] +
               g_hr[((size_t)N + i) * H0 + f] +
               g_hr[((size_t)2 * N + i) * H0 + f]) * (1.f / 3.f);
    hp[rr][f] = 1.f / (1.f + expf(-v));
    __syncthreads();
    float acc = 0.f;
#pragma unroll 16
    for (int k = 0; k < H0; k++) acc = fmaf(hp[rr][k], Wg0[k * H1 + f], acc);
    g_support[(size_t)i * H1 + f] = acc;
}

// ================= kernel 4: gnn layer 1 (warp/row, MLP=8, smem weights) ===
__global__ void __launch_bounds__(256)
gnn1_kernel(const float* __restrict__ bg0,
            const float* __restrict__ br) {
    __shared__ int    sidx[8][CAP];
    __shared__ float  shp[8][H1];
    __shared__ float2 scw[H1 * H2];   // 16 KB combined weights
    int tid = threadIdx.x;
    int lane = tid & 31, wid = tid >> 5;
    int i = blockIdx.x * 8 + wid;

    // stage combined weights (block-cooperative, no barrier needed yet)
    {
        const float4* src = (const float4*)g_WgC;
        float4* dst = (float4*)scw;
#pragma unroll
        for (int q = 0; q < 4; q++) dst[tid + q * 256] = src[tid + q * 256];
    }

    int total = g_nbr_cnt[i];
    int cnt = min(total, CAP);
    const int* gl = g_nbr_idx + (size_t)i * CAP;
    for (int k = lane; k < cnt; k += 32) sidx[wid][k] = gl[k];
    __syncwarp();

    const float2* sup = (const float2*)g_support;
    float2 a0 = {0.f, 0.f}, a1 = {0.f, 0.f}, a2 = {0.f, 0.f}, a3 = {0.f, 0.f};
    float2 a4 = {0.f, 0.f}, a5 = {0.f, 0.f}, a6 = {0.f, 0.f}, a7 = {0.f, 0.f};
    int k = 0;
    for (; k + 8 <= cnt; k += 8) {
        int4 j0 = *(const int4*)&sidx[wid][k];
        int4 j1 = *(const int4*)&sidx[wid][k + 4];
        float2 p0 = sup[(size_t)j0.x * 32 + lane];
        float2 p1 = sup[(size_t)j0.y * 32 + lane];
        float2 p2 = sup[(size_t)j0.z * 32 + lane];
        float2 p3 = sup[(size_t)j0.w * 32 + lane];
        float2 p4 = sup[(size_t)j1.x * 32 + lane];
        float2 p5 = sup[(size_t)j1.y * 32 + lane];
        float2 p6 = sup[(size_t)j1.z * 32 + lane];
        float2 p7 = sup[(size_t)j1.w * 32 + lane];
        a0.x += p0.x; a0.y += p0.y;  a1.x += p1.x; a1.y += p1.y;
        a2.x += p2.x; a2.y += p2.y;  a3.x += p3.x; a3.y += p3.y;
        a4.x += p4.x; a4.y += p4.y;  a5.x += p5.x; a5.y += p5.y;
        a6.x += p6.x; a6.y += p6.y;  a7.x += p7.x; a7.y += p7.y;
    }
    for (; k + 4 <= cnt; k += 4) {
        int4 j0 = *(const int4*)&sidx[wid][k];
        float2 p0 = sup[(size_t)j0.x * 32 + lane];
        float2 p1 = sup[(size_t)j0.y * 32 + lane];
        float2 p2 = sup[(size_t)j0.z * 32 + lane];
        float2 p3 = sup[(size_t)j0.w * 32 + lane];
        a0.x += p0.x; a0.y += p0.y;  a1.x += p1.x; a1.y += p1.y;
        a2.x += p2.x; a2.y += p2.y;  a3.x += p3.x; a3.y += p3.y;
    }
    for (; k < cnt; k++) {
        float2 p = sup[(size_t)sidx[wid][k] * 32 + lane];
        a0.x += p.x; a0.y += p.y;
    }
    float dinv = 1.f / (float)total;
    float2 bg = ((const float2*)bg0)[lane];
    float2 h;
    h.x = leaky((a0.x + a1.x + a2.x + a3.x + a4.x + a5.x + a6.x + a7.x) * dinv + bg.x);
    h.y = leaky((a0.y + a1.y + a2.y + a3.y + a4.y + a5.y + a6.y + a7.y) * dinv + bg.y);
    *(float2*)&shp[wid][2 * lane] = h;
    __syncthreads();   // weights staged + shp visible

    // epilogue: all from shared memory
    float s2 = 0.f, rr2 = 0.f;
#pragma unroll
    for (int kk = 0; kk < H1; kk += 4) {
        float4 hv = *(const float4*)&shp[wid][kk];
        float2 w0 = scw[(kk + 0) * H2 + lane];
        float2 w1 = scw[(kk + 1) * H2 + lane];
        float2 w2 = scw[(kk + 2) * H2 + lane];
        float2 w3 = scw[(kk + 3) * H2 + lane];
        s2  = fmaf(hv.x, w0.x, s2);  rr2 = fmaf(hv.x, w0.y, rr2);
        s2  = fmaf(hv.y, w1.x, s2);  rr2 = fmaf(hv.y, w1.y, rr2);
        s2  = fmaf(hv.z, w2.x, s2);  rr2 = fmaf(hv.z, w2.y, rr2);
        s2  = fmaf(hv.w, w3.x, s2);  rr2 = fmaf(hv.w, w3.y, rr2);
    }
    g_support2[(size_t)i * H2 + lane] = s2;
    g_resid[(size_t)i * H2 + lane]    = rr2 + br[lane];
}

// ================= kernel 5: gnn layer 2 + residual -> out (MLP=16) =======
__global__ void __launch_bounds__(256)
gnn2_kernel(const float* __restrict__ bg1,
            float* __restrict__ out) {
    __shared__ int sidx[8][CAP];
    int tid = threadIdx.x;
    int lane = tid & 31, wid = tid >> 5;
    int i = blockIdx.x * 8 + wid;
    int total = g_nbr_cnt[i];
    int cnt = min(total, CAP);
    const int* gl = g_nbr_idx + (size_t)i * CAP;
    for (int k = lane; k < cnt; k += 32) sidx[wid][k] = gl[k];
    __syncwarp();

    const float* sup2 = g_support2;
    float a0 = 0.f, a1 = 0.f, a2 = 0.f, a3 = 0.f;
    float a4 = 0.f, a5 = 0.f, a6 = 0.f, a7 = 0.f;
    float b0 = 0.f, b1 = 0.f, b2 = 0.f, b3 = 0.f;
    float b4 = 0.f, b5 = 0.f, b6 = 0.f, b7 = 0.f;
    int k = 0;
    for (; k + 16 <= cnt; k += 16) {
        int4 j0 = *(const int4*)&sidx[wid][k];
        int4 j1 = *(const int4*)&sidx[wid][k + 4];
        int4 j2 = *(const int4*)&sidx[wid][k + 8];
        int4 j3 = *(const int4*)&sidx[wid][k + 12];
        a0 += sup2[(size_t)j0.x * H2 + lane];
        a1 += sup2[(size_t)j0.y * H2 + lane];
        a2 += sup2[(size_t)j0.z * H2 + lane];
        a3 += sup2[(size_t)j0.w * H2 + lane];
        a4 += sup2[(size_t)j1.x * H2 + lane];
        a5 += sup2[(size_t)j1.y * H2 + lane];
        a6 += sup2[(size_t)j1.z * H2 + lane];
        a7 += sup2[(size_t)j1.w * H2 + lane];
        b0 += sup2[(size_t)j2.x * H2 + lane];
        b1 += sup2[(size_t)j2.y * H2 + lane];
        b2 += sup2[(size_t)j2.z * H2 + lane];
        b3 += sup2[(size_t)j2.w * H2 + lane];
        b4 += sup2[(size_t)j3.x * H2 + lane];
        b5 += sup2[(size_t)j3.y * H2 + lane];
        b6 += sup2[(size_t)j3.z * H2 + lane];
        b7 += sup2[(size_t)j3.w * H2 + lane];
    }
    for (; k + 4 <= cnt; k += 4) {
        int4 j0 = *(const int4*)&sidx[wid][k];
        a0 += sup2[(size_t)j0.x * H2 + lane];
        a1 += sup2[(size_t)j0.y * H2 + lane];
        a2 += sup2[(size_t)j0.z * H2 + lane];
        a3 += sup2[(size_t)j0.w * H2 + lane];
    }
    for (; k < cnt; k++) a0 += sup2[(size_t)sidx[wid][k] * H2 + lane];

    float agg = (a0 + a1 + a2 + a3 + a4 + a5 + a6 + a7)
              + (b0 + b1 + b2 + b3 + b4 + b5 + b6 + b7);
    float v = leaky(agg * (1.f / (float)total) + bg1[lane]);
    out[(size_t)i * H2 + lane] = v + g_resid[(size_t)i * H2 + lane];
}

extern "C" void kernel_launch(void* const* d_in, const int* in_sizes, int n_in,
                              void* d_out, int out_size) {
    const float* x   = (const float*)d_in[0];
    const float* adj = (const float*)d_in[1];
    const float* W1  = (const float*)d_in[2];
    const float* a1  = (const float*)d_in[3];
    const float* W2  = (const float*)d_in[4];
    const float* a2  = (const float*)d_in[5];
    const float* W3  = (const float*)d_in[6];
    const float* a3  = (const float*)d_in[7];
    const float* Wg0 = (const float*)d_in[8];
    const float* bg0 = (const float*)d_in[9];
    const float* Wg1 = (const float*)d_in[10];
    const float* bg1 = (const float*)d_in[11];
    const float* Wr  = (const float*)d_in[12];
    const float* br  = (const float*)d_in[13];
    const void*  rel = d_in[14];
    float* out = (float*)d_out;

    wh_kernel<<<dim3(64, 3), 256>>>(x, W1, a1, W2, a2, W3, a3);
    scan_attn_kernel<<<3 * N, 256>>>(adj, rel);
    fuse_kernel<<<N / 4, 256>>>(Wg0, Wg1, Wr);
    gnn1_kernel<<<N / 8, 256>>>(bg0, br);
    gnn2_kernel<<<N / 8, 256>>>(bg1, out);
}